// round 12
// baseline (speedup 1.0000x reference)
#include <cuda_runtime.h>

// TransformDomainInterpolator, GB300 (sm_103a). Single persistent-shaped kernel.
//
// Math: fc = M/2 keeps ALL 2048 DFT bins -> exact 2x bandlimited interp:
//   out[2m]   = x[m]
//   out[2m+1] = IDFT2048( DFT2048(x)[k] * w[k] )/2048,
//     w[k] = e^{+i*pi*k/2048} (k<1024), -e^{+i*pi*k/2048} (k>=1024)
// Time: out[t] = lerp(H2, H11, clamp((t-2)/9, 0, 1)).
//
// Plan: 512 blocks x 256 threads, 4 blocks/SM (launch_bounds(256,4) -> 64
// regs, NO spills; 592 slots >= 512 -> ONE wave). Each block runs BOTH row
// FFTs sequentially (tw reused), parks row0 odd-values in smem, writes all
// 14 output symbols itself (t=0..2 overlapped with row1 FFT). No scratch.

#define MM 2048
#define NSYM 14
#define PADN 2176
#define PIDX(i) ((i) + ((i) >> 4))
#define C8v  0.70710678118654752f
#define CP8v 0.92387953251128676f
#define SP8v 0.38268343236508977f

static __device__ __forceinline__ float2 cmul(float2 a, float2 b) {
    return make_float2(fmaf(a.x, b.x, -a.y * b.y), fmaf(a.x, b.y, a.y * b.x));
}
static __device__ __forceinline__ float2 cadd(float2 a, float2 b) {
    return make_float2(a.x + b.x, a.y + b.y);
}
static __device__ __forceinline__ float2 csub(float2 a, float2 b) {
    return make_float2(a.x - b.x, a.y - b.y);
}

// ---- radix-4 fused DIF stages (S+1, S)
template <int S>
static __device__ __forceinline__ void fwd4(float2* __restrict__ y,
                                            const float2* __restrict__ tw, int g)
{
    const int h1 = 1 << S;
    const int j  = g & (h1 - 1);
    const int i0 = ((g >> S) << (S + 2)) | j;
    float2 w  = tw[j << (9 - S)];
    float2 wm = make_float2(w.y, -w.x);
    float2 v  = tw[j << (10 - S)];
    float2 a = y[PIDX(i0)], bb = y[PIDX(i0 + h1)];
    float2 c = y[PIDX(i0 + 2 * h1)], d = y[PIDX(i0 + 3 * h1)];
    float2 a1 = cadd(a, c),  c1 = cmul(csub(a, c), w);
    float2 b1 = cadd(bb, d), d1 = cmul(csub(bb, d), wm);
    y[PIDX(i0)]          = cadd(a1, b1);
    y[PIDX(i0 + h1)]     = cmul(csub(a1, b1), v);
    y[PIDX(i0 + 2 * h1)] = cadd(c1, d1);
    y[PIDX(i0 + 3 * h1)] = cmul(csub(c1, d1), v);
}

// ---- radix-4 fused DIT stages (S, S+1), conjugate twiddles
template <int S>
static __device__ __forceinline__ void inv4(float2* __restrict__ y,
                                            const float2* __restrict__ tw, int g)
{
    const int h1 = 1 << S;
    const int j  = g & (h1 - 1);
    const int i0 = ((g >> S) << (S + 2)) | j;
    float2 w   = tw[j << (9 - S)];
    float2 cw  = make_float2(w.x, -w.y);
    float2 cw2 = make_float2(w.y, w.x);
    float2 v0  = tw[j << (10 - S)];
    float2 cv  = make_float2(v0.x, -v0.y);
    float2 a = y[PIDX(i0)], bb = y[PIDX(i0 + h1)];
    float2 c = y[PIDX(i0 + 2 * h1)], d = y[PIDX(i0 + 3 * h1)];
    float2 t  = cmul(bb, cv);
    float2 a1 = cadd(a, t), b1 = csub(a, t);
    t = cmul(d, cv);
    float2 c1 = cadd(c, t), d1 = csub(c, t);
    t = cmul(c1, cw);
    y[PIDX(i0)]          = cadd(a1, t);
    y[PIDX(i0 + 2 * h1)] = csub(a1, t);
    t = cmul(d1, cw2);
    y[PIDX(i0 + h1)]     = cadd(b1, t);
    y[PIDX(i0 + 3 * h1)] = csub(b1, t);
}

// ---- radix-8 fused DIF stages (S+2, S+1, S)
template <int S>
static __device__ __forceinline__ void fwd8(float2* __restrict__ y,
                                            const float2* __restrict__ tw, int q)
{
    const int h  = 1 << S;
    const int j  = q & (h - 1);
    const int i0 = ((q >> S) << (S + 3)) | j;
    float2 x[8];
    #pragma unroll
    for (int r = 0; r < 8; ++r) x[r] = y[PIDX(i0 + r * h)];
    #pragma unroll
    for (int r = 0; r < 4; ++r) {
        float2 wa = tw[(j + r * h) << (8 - S)];
        float2 u = x[r], v = x[r + 4];
        x[r] = cadd(u, v);
        x[r + 4] = cmul(csub(u, v), wa);
    }
    float2 wb0 = tw[j << (9 - S)];
    float2 wb1 = make_float2(wb0.y, -wb0.x);
    #pragma unroll
    for (int o = 0; o < 8; o += 4) {
        float2 u = x[o], v = x[o + 2];
        x[o] = cadd(u, v); x[o + 2] = cmul(csub(u, v), wb0);
        u = x[o + 1]; v = x[o + 3];
        x[o + 1] = cadd(u, v); x[o + 3] = cmul(csub(u, v), wb1);
    }
    float2 wc = tw[j << (10 - S)];
    #pragma unroll
    for (int g = 0; g < 4; ++g) {
        float2 u = x[2 * g], v = x[2 * g + 1];
        x[2 * g] = cadd(u, v); x[2 * g + 1] = cmul(csub(u, v), wc);
    }
    #pragma unroll
    for (int r = 0; r < 8; ++r) y[PIDX(i0 + r * h)] = x[r];
}

// ---- radix-8 fused DIT stages (S, S+1, S+2), conjugate twiddles
template <int S>
static __device__ __forceinline__ void inv8(float2* __restrict__ y,
                                            const float2* __restrict__ tw, int q)
{
    const int h  = 1 << S;
    const int j  = q & (h - 1);
    const int i0 = ((q >> S) << (S + 3)) | j;
    float2 x[8];
    #pragma unroll
    for (int r = 0; r < 8; ++r) x[r] = y[PIDX(i0 + r * h)];
    float2 wc0 = tw[j << (10 - S)];
    float2 wc  = make_float2(wc0.x, -wc0.y);
    #pragma unroll
    for (int g = 0; g < 4; ++g) {
        float2 v = cmul(x[2 * g + 1], wc);
        float2 u = x[2 * g];
        x[2 * g] = cadd(u, v); x[2 * g + 1] = csub(u, v);
    }
    float2 wb0  = tw[j << (9 - S)];
    float2 wb0c = make_float2(wb0.x, -wb0.y);
    float2 wb1c = make_float2(wb0.y, wb0.x);
    #pragma unroll
    for (int o = 0; o < 8; o += 4) {
        float2 v = cmul(x[o + 2], wb0c);
        float2 u = x[o];
        x[o] = cadd(u, v); x[o + 2] = csub(u, v);
        v = cmul(x[o + 3], wb1c);
        u = x[o + 1];
        x[o + 1] = cadd(u, v); x[o + 3] = csub(u, v);
    }
    #pragma unroll
    for (int r = 0; r < 4; ++r) {
        float2 wa0 = tw[(j + r * h) << (8 - S)];
        float2 wac = make_float2(wa0.x, -wa0.y);
        float2 v = cmul(x[r + 4], wac);
        float2 u = x[r];
        x[r] = cadd(u, v); x[r + 4] = csub(u, v);
    }
    #pragma unroll
    for (int r = 0; r < 8; ++r) y[PIDX(i0 + r * h)] = x[r];
}

// ---- Full forward+pointwise+inverse pass for one pilot row.
// Loads pilots from (rbr, ibr); result (odd interp values, natural order
// m = q + 256*r) left in x[]. First __syncthreads also guards y reuse.
static __device__ __forceinline__ void fft_row(
    const float* __restrict__ rbr, const float* __restrict__ ibr,
    float2* __restrict__ y, const float2* __restrict__ tw,
    int q, float2* __restrict__ x)
{
    #pragma unroll
    for (int r = 0; r < 8; ++r)
        x[r] = make_float2(rbr[q + 256 * r], ibr[q + 256 * r]);
    __syncthreads();   // tw ready (row0) / y free (row1)

    // ---- P1: fwd stages 10,9,8 from registers
    #pragma unroll
    for (int r = 0; r < 4; ++r) {
        float2 wa = tw[q + 256 * r];
        float2 u = x[r], v = x[r + 4];
        x[r] = cadd(u, v);
        x[r + 4] = cmul(csub(u, v), wa);
    }
    {
        float2 wb0 = tw[q << 1];
        float2 wb1 = make_float2(wb0.y, -wb0.x);
        #pragma unroll
        for (int o = 0; o < 8; o += 4) {
            float2 u = x[o], v = x[o + 2];
            x[o] = cadd(u, v); x[o + 2] = cmul(csub(u, v), wb0);
            u = x[o + 1]; v = x[o + 3];
            x[o + 1] = cadd(u, v); x[o + 3] = cmul(csub(u, v), wb1);
        }
        float2 wc = tw[q << 2];
        #pragma unroll
        for (int g = 0; g < 4; ++g) {
            float2 u = x[2 * g], v = x[2 * g + 1];
            x[2 * g] = cadd(u, v); x[2 * g + 1] = cmul(csub(u, v), wc);
        }
    }
    #pragma unroll
    for (int r = 0; r < 8; ++r) y[PIDX(q + 256 * r)] = x[r];
    __syncthreads();

    fwd8<5>(y, tw, q);                                // stages 7,6,5
    __syncthreads();
    fwd4<3>(y, tw, 2 * q); fwd4<3>(y, tw, 2 * q + 1); // stages 4,3
    __syncthreads();

    // ---- MID: fwd 2,1,0 + pointwise + inv 0,1,2 on 8 contiguous elems
    {
        const int p = 8 * q;
        #pragma unroll
        for (int r = 0; r < 8; ++r) x[r] = y[PIDX(p + r)];
        { float2 u=x[0], v=x[4]; x[0]=cadd(u,v); x[4]=csub(u,v); }
        { float2 u=x[1], v=x[5]; x[1]=cadd(u,v);
          x[5]=cmul(csub(u,v), make_float2(C8v,-C8v)); }
        { float2 u=x[2], v=x[6]; x[2]=cadd(u,v);
          float2 t=csub(u,v); x[6]=make_float2(t.y,-t.x); }
        { float2 u=x[3], v=x[7]; x[3]=cadd(u,v);
          x[7]=cmul(csub(u,v), make_float2(-C8v,-C8v)); }
        #pragma unroll
        for (int o = 0; o < 8; o += 4) {
            float2 u=x[o], v=x[o+2]; x[o]=cadd(u,v); x[o+2]=csub(u,v);
            u=x[o+1]; v=x[o+3]; x[o+1]=cadd(u,v);
            float2 t=csub(u,v); x[o+3]=make_float2(t.y,-t.x);
        }
        #pragma unroll
        for (int g = 0; g < 4; ++g) {
            float2 u=x[2*g], v=x[2*g+1];
            x[2*g]=cadd(u,v); x[2*g+1]=csub(u,v);
        }
        {
            const float K = 1.0f / 2048.0f;
            int kq = (int)(__brev((unsigned)q) >> 24);
            float sv, cv;
            sincospif((float)kq * (1.0f / 2048.0f), &sv, &cv);
            float2 base = make_float2(cv, sv);        // e^{+i*pi*kq/2048}
            const float2 S8[8] = {
                { K, 0.0f }, { 0.0f, -K },
                { K*C8v,  K*C8v }, { K*C8v, -K*C8v },
                { K*CP8v, K*SP8v }, { K*SP8v, -K*CP8v },
                { K*SP8v, K*CP8v }, { K*CP8v, -K*SP8v } };
            #pragma unroll
            for (int r = 0; r < 8; ++r) x[r] = cmul(x[r], cmul(base, S8[r]));
        }
        #pragma unroll
        for (int g = 0; g < 4; ++g) {
            float2 u=x[2*g], v=x[2*g+1];
            x[2*g]=cadd(u,v); x[2*g+1]=csub(u,v);
        }
        #pragma unroll
        for (int o = 0; o < 8; o += 4) {
            float2 u=x[o], v=x[o+2]; x[o]=cadd(u,v); x[o+2]=csub(u,v);
            u=x[o+1]; v=make_float2(-x[o+3].y, x[o+3].x);
            x[o+1]=cadd(u,v); x[o+3]=csub(u,v);
        }
        { float2 u=x[0], v=x[4]; x[0]=cadd(u,v); x[4]=csub(u,v); }
        { float2 u=x[1], v=cmul(x[5], make_float2(C8v,C8v));
          x[1]=cadd(u,v); x[5]=csub(u,v); }
        { float2 u=x[2], v=make_float2(-x[6].y, x[6].x);
          x[2]=cadd(u,v); x[6]=csub(u,v); }
        { float2 u=x[3], v=cmul(x[7], make_float2(-C8v,C8v));
          x[3]=cadd(u,v); x[7]=csub(u,v); }
        #pragma unroll
        for (int r = 0; r < 8; ++r) y[PIDX(p + r)] = x[r];
    }
    __syncthreads();

    inv4<3>(y, tw, 2 * q); inv4<3>(y, tw, 2 * q + 1); // stages 3,4
    __syncthreads();
    inv8<5>(y, tw, q);                                // stages 5,6,7
    __syncthreads();

    // ---- iP1: inv stages 8,9,10 -> ends in REGISTERS, natural m = q+256r.
    {
        #pragma unroll
        for (int r = 0; r < 8; ++r) x[r] = y[PIDX(q + 256 * r)];
        float2 wc0 = tw[q << 2];
        float2 wc  = make_float2(wc0.x, -wc0.y);
        #pragma unroll
        for (int g = 0; g < 4; ++g) {
            float2 v = cmul(x[2*g+1], wc);
            float2 u = x[2*g];
            x[2*g] = cadd(u, v); x[2*g+1] = csub(u, v);
        }
        float2 wb0  = tw[q << 1];
        float2 wb0c = make_float2(wb0.x, -wb0.y);
        float2 wb1c = make_float2(wb0.y, wb0.x);
        #pragma unroll
        for (int o = 0; o < 8; o += 4) {
            float2 v = cmul(x[o+2], wb0c);
            float2 u = x[o];
            x[o] = cadd(u, v); x[o+2] = csub(u, v);
            v = cmul(x[o+3], wb1c);
            u = x[o+1];
            x[o+1] = cadd(u, v); x[o+3] = csub(u, v);
        }
        #pragma unroll
        for (int r = 0; r < 4; ++r) {
            float2 wa0 = tw[q + 256 * r];
            float2 wac = make_float2(wa0.x, -wa0.y);
            float2 v = cmul(x[r+4], wac);
            float2 u = x[r];
            x[r] = cadd(u, v); x[r+4] = csub(u, v);
        }
    }
}

// MODE 0: real-only f32 output. MODE 1: interleaved complex-as-f32 output.
template <int MODE>
__global__ void __launch_bounds__(256, 4) tdi_kernel(
    const float* __restrict__ re,
    const float* __restrict__ im,
    void* __restrict__ outv)
{
    __shared__ float2 tw[1024];
    __shared__ float2 ys[PADN];
    __shared__ float2 dbuf[MM];       // row0 odd-values parked here

    const int b = blockIdx.x;
    const int q = threadIdx.x;

    for (int t = q; t < 1024; t += 256) {
        float s, c;
        sincospif(-(float)t * (1.0f / 1024.0f), &s, &c);
        tw[t] = make_float2(c, s);
    }

    const float* rb = re + (size_t)b * 4096;
    const float* ib = im + (size_t)b * 4096;

    float2 x[8];

    // ===== Row 0 (symbol 2) =====
    fft_row(rb, ib, ys, tw, q, x);

    // Park d2 and write the 3 row0-only symbols (t=0,1,2; a=0).
    #pragma unroll
    for (int r = 0; r < 8; ++r) {
        int m = q + 256 * r;
        dbuf[m] = x[r];
        if (MODE == 0) {
            float2 v = make_float2(rb[m], x[r].x);
            #pragma unroll
            for (int tt = 0; tt < 3; ++tt)
                ((float2*)outv)[((size_t)b * NSYM + tt) * MM + m] = v;
        } else {
            float4 v = make_float4(rb[m], ib[m], x[r].x, x[r].y);
            #pragma unroll
            for (int tt = 0; tt < 3; ++tt)
                ((float4*)outv)[((size_t)b * NSYM + tt) * MM + m] = v;
        }
    }

    // ===== Row 1 (symbol 11) =====  (fft_row's first sync guards ys reuse)
    fft_row(rb + MM, ib + MM, ys, tw, q, x);

    // Write t=11..13 (row1 only) and t=3..10 (lerp; dbuf read is same-thread).
    #pragma unroll
    for (int r = 0; r < 8; ++r) {
        int m = q + 256 * r;
        if (MODE == 0) {
            float e11 = rb[MM + m], d11 = x[r].x;
            float2 v1 = make_float2(e11, d11);
            #pragma unroll
            for (int tt = 11; tt < 14; ++tt)
                ((float2*)outv)[((size_t)b * NSYM + tt) * MM + m] = v1;
            float e2 = rb[m], d2 = dbuf[m].x;
            float de = e11 - e2, dd = d11 - d2;
            #pragma unroll
            for (int t = 3; t <= 10; ++t) {
                float a = (float)(t - 2) * (1.0f / 9.0f);
                float2 v = make_float2(fmaf(a, de, e2), fmaf(a, dd, d2));
                ((float2*)outv)[((size_t)b * NSYM + t) * MM + m] = v;
            }
        } else {
            float2 e11 = make_float2(rb[MM + m], ib[MM + m]);
            float2 d11 = x[r];
            float4 v1 = make_float4(e11.x, e11.y, d11.x, d11.y);
            #pragma unroll
            for (int tt = 11; tt < 14; ++tt)
                ((float4*)outv)[((size_t)b * NSYM + tt) * MM + m] = v1;
            float2 e2 = make_float2(rb[m], ib[m]);
            float2 d2 = dbuf[m];
            float2 de = csub(e11, e2), dd = csub(d11, d2);
            #pragma unroll
            for (int t = 3; t <= 10; ++t) {
                float a = (float)(t - 2) * (1.0f / 9.0f);
                float4 v = make_float4(fmaf(a, de.x, e2.x), fmaf(a, de.y, e2.y),
                                       fmaf(a, dd.x, d2.x), fmaf(a, dd.y, d2.y));
                ((float4*)outv)[((size_t)b * NSYM + t) * MM + m] = v;
            }
        }
    }
}

extern "C" void kernel_launch(void* const* d_in, const int* in_sizes, int n_in,
                              void* d_out, int out_size)
{
    const float* re = (const float*)d_in[0];
    const float* im = (const float*)d_in[1];
    const int B = in_sizes[0] / 4096;
    const long long interleaved = (long long)B * NSYM * 4096 * 2;

    if ((long long)out_size >= interleaved)
        tdi_kernel<1><<<B, 256>>>(re, im, d_out);
    else
        tdi_kernel<0><<<B, 256>>>(re, im, d_out);
}

// round 13
// speedup vs baseline: 1.0490x; 1.0490x over previous
#include <cuda_runtime.h>

// TransformDomainInterpolator, GB300 (sm_103a). Two-kernel split, spill-free.
//
// Math: fc = M/2 keeps ALL 2048 DFT bins -> exact 2x bandlimited interp:
//   out[2m]   = x[m]
//   out[2m+1] = IDFT2048( DFT2048(x)[k] * w[k] )/2048,
//     w[k] = e^{+i*pi*k/2048} (k<1024), -e^{+i*pi*k/2048} (k>=1024)
// Time: out[t] = lerp(H2, H11, clamp((t-2)/9, 0, 1)).
//
// k1: one 256-thread block per (batch,row) FFT; 1024 blocks -> ONE wave at
//     7 blocks/SM (87.5% occ ceiling). Radix-4 phases keep only 8 data regs
//     in flight -> fits the 36-reg cap WITHOUT spills (R11's k1 bug).
//     Writes odd values to scratch + its 3 row-exclusive output symbols.
// k2: streaming lerp for t=3..10 (measured at the LTS ceiling already).

#define MM 2048
#define NSYM 14
#define PADN 2176
#define PIDX(i) ((i) + ((i) >> 4))

__device__ float g_scratch[512 * 4096 * 2];   // MODE0 uses first 8MB as float

static __device__ __forceinline__ float2 cmul(float2 a, float2 b) {
    return make_float2(fmaf(a.x, b.x, -a.y * b.y), fmaf(a.x, b.y, a.y * b.x));
}
static __device__ __forceinline__ float2 cadd(float2 a, float2 b) {
    return make_float2(a.x + b.x, a.y + b.y);
}
static __device__ __forceinline__ float2 csub(float2 a, float2 b) {
    return make_float2(a.x - b.x, a.y - b.y);
}

// ---- radix-4 fused DIF stages (S+1, S); 8 data regs in flight
template <int S>
static __device__ __forceinline__ void fwd4(float2* __restrict__ y,
                                            const float2* __restrict__ tw, int g)
{
    const int h1 = 1 << S;
    const int j  = g & (h1 - 1);
    const int i0 = ((g >> S) << (S + 2)) | j;
    float2 w  = tw[j << (9 - S)];
    float2 wm = make_float2(w.y, -w.x);          // -i * w
    float2 v  = tw[j << (10 - S)];
    float2 a = y[PIDX(i0)], bb = y[PIDX(i0 + h1)];
    float2 c = y[PIDX(i0 + 2 * h1)], d = y[PIDX(i0 + 3 * h1)];
    float2 a1 = cadd(a, c),  c1 = cmul(csub(a, c), w);
    float2 b1 = cadd(bb, d), d1 = cmul(csub(bb, d), wm);
    y[PIDX(i0)]          = cadd(a1, b1);
    y[PIDX(i0 + h1)]     = cmul(csub(a1, b1), v);
    y[PIDX(i0 + 2 * h1)] = cadd(c1, d1);
    y[PIDX(i0 + 3 * h1)] = cmul(csub(c1, d1), v);
}

// ---- radix-4 fused DIT stages (S, S+1), conjugate twiddles
template <int S>
static __device__ __forceinline__ void inv4(float2* __restrict__ y,
                                            const float2* __restrict__ tw, int g)
{
    const int h1 = 1 << S;
    const int j  = g & (h1 - 1);
    const int i0 = ((g >> S) << (S + 2)) | j;
    float2 w   = tw[j << (9 - S)];
    float2 cw  = make_float2(w.x, -w.y);         // conj(w)
    float2 cw2 = make_float2(w.y, w.x);          // i * conj(w)
    float2 v0  = tw[j << (10 - S)];
    float2 cv  = make_float2(v0.x, -v0.y);
    float2 a = y[PIDX(i0)], bb = y[PIDX(i0 + h1)];
    float2 c = y[PIDX(i0 + 2 * h1)], d = y[PIDX(i0 + 3 * h1)];
    float2 t  = cmul(bb, cv);
    float2 a1 = cadd(a, t), b1 = csub(a, t);
    t = cmul(d, cv);
    float2 c1 = cadd(c, t), d1 = csub(c, t);
    t = cmul(c1, cw);
    y[PIDX(i0)]          = cadd(a1, t);
    y[PIDX(i0 + 2 * h1)] = csub(a1, t);
    t = cmul(d1, cw2);
    y[PIDX(i0 + h1)]     = cadd(b1, t);
    y[PIDX(i0 + 3 * h1)] = csub(b1, t);
}

// ============================ k1: per-row FFT ============================
// grid = 2*B, 256 threads. block -> (batch = bid>>1, row = bid&1).
template <int MODE>
__global__ void __launch_bounds__(256, 7) tdi_fft_kernel(
    const float* __restrict__ re,
    const float* __restrict__ im,
    void* __restrict__ outv)
{
    __shared__ float2 tw[1024];      // e^{-i*pi*t/1024}
    __shared__ float2 y[PADN];

    const int batch = blockIdx.x >> 1;
    const int row   = blockIdx.x & 1;
    const int q     = threadIdx.x;

    for (int t = q; t < 1024; t += 256) {
        float s, c;
        sincospif(-(float)t * (1.0f / 1024.0f), &s, &c);
        tw[t] = make_float2(c, s);
    }

    const float* rbr = re + (size_t)batch * 4096 + row * MM;
    const float* ibr = im + (size_t)batch * 4096 + row * MM;

    // Load pilots into padded smem (natural order)
    #pragma unroll
    for (int r = 0; r < 8; ++r) {
        int m = q + 256 * r;
        y[PIDX(m)] = make_float2(rbr[m], ibr[m]);
    }
    __syncthreads();

    // ---- forward DIF: stage pairs (10,9)(8,7)(6,5)(4,3)(2,1)
    fwd4<9>(y, tw, q); fwd4<9>(y, tw, q + 256); __syncthreads();
    fwd4<7>(y, tw, q); fwd4<7>(y, tw, q + 256); __syncthreads();
    fwd4<5>(y, tw, q); fwd4<5>(y, tw, q + 256); __syncthreads();
    fwd4<3>(y, tw, q); fwd4<3>(y, tw, q + 256); __syncthreads();
    fwd4<1>(y, tw, q); fwd4<1>(y, tw, q + 256); __syncthreads();

    // ---- MID: fwd s0 (w=1) + pointwise twiddle + inv s0 (w=1), on pairs.
    // Position p holds X[bitrev11(p)]; p even -> k<1024 (+), p odd -> -(...)
    #pragma unroll
    for (int it = 0; it < 4; ++it) {
        int p = 2 * (q + 256 * it);
        int k = (int)(__brev((unsigned)p) >> 21);
        float sv, cv;
        sincospif((float)k * (1.0f / 2048.0f), &sv, &cv);
        float2 base  = make_float2(cv * (1.0f / 2048.0f), sv * (1.0f / 2048.0f));
        float2 baseo = make_float2(base.y, -base.x);       // -i * base
        float2 a = y[PIDX(p)], bb = y[PIDX(p + 1)];
        float2 A = cmul(cadd(a, bb), base);
        float2 Bv = cmul(csub(a, bb), baseo);
        y[PIDX(p)]     = cadd(A, Bv);
        y[PIDX(p + 1)] = csub(A, Bv);
    }
    __syncthreads();

    // ---- inverse DIT: stage pairs (1,2)(3,4)(5,6)(7,8)(9,10)
    inv4<1>(y, tw, q); inv4<1>(y, tw, q + 256); __syncthreads();
    inv4<3>(y, tw, q); inv4<3>(y, tw, q + 256); __syncthreads();
    inv4<5>(y, tw, q); inv4<5>(y, tw, q + 256); __syncthreads();
    inv4<7>(y, tw, q); inv4<7>(y, tw, q + 256); __syncthreads();
    inv4<9>(y, tw, q); inv4<9>(y, tw, q + 256);
    // no sync: inv4<9> groups {q, q+256} produced exactly m = q + 256*r
    // (r=0..7) -> epilogue reads are same-thread.

    // ---- Epilogue: scratch + the 3 row-exclusive output symbols
    const int t0 = row ? 11 : 0;
    if (MODE == 0) {
        float* scr = g_scratch + ((size_t)batch * 2 + row) * MM;
        #pragma unroll
        for (int r = 0; r < 8; ++r) {
            int m = q + 256 * r;
            float d = y[PIDX(m)].x;
            scr[m] = d;
            float2 v = make_float2(rbr[m], d);
            #pragma unroll
            for (int tt = 0; tt < 3; ++tt)
                ((float2*)outv)[((size_t)batch * NSYM + t0 + tt) * MM + m] = v;
        }
    } else {
        float2* scr = (float2*)g_scratch + ((size_t)batch * 2 + row) * MM;
        #pragma unroll
        for (int r = 0; r < 8; ++r) {
            int m = q + 256 * r;
            float2 d = y[PIDX(m)];
            scr[m] = d;
            float4 v = make_float4(rbr[m], ibr[m], d.x, d.y);
            #pragma unroll
            for (int tt = 0; tt < 3; ++tt)
                ((float4*)outv)[((size_t)batch * NSYM + t0 + tt) * MM + m] = v;
        }
    }
}

// ===================== k2: streaming lerp, t = 3..10 =====================
// grid = 4*B, 256 threads; block covers 512 m-values of one batch.
template <int MODE>
__global__ void __launch_bounds__(256) tdi_lerp_kernel(
    const float* __restrict__ re,
    const float* __restrict__ im,
    void* __restrict__ outv)
{
    const int b    = blockIdx.x >> 2;
    const int part = blockIdx.x & 3;
    const int tid  = threadIdx.x;
    const float* rb = re + (size_t)b * 4096;
    const float* ib = im + (size_t)b * 4096;

    #pragma unroll
    for (int s = 0; s < 2; ++s) {
        int m = part * 512 + tid + 256 * s;
        if (MODE == 0) {
            const float* scr = g_scratch + (size_t)b * 2 * MM;
            float e2  = rb[m],  e11 = rb[MM + m];
            float d2  = scr[m], d11 = scr[MM + m];
            float de = e11 - e2, dd = d11 - d2;
            #pragma unroll
            for (int t = 3; t <= 10; ++t) {
                float a = (float)(t - 2) * (1.0f / 9.0f);
                float2 v = make_float2(fmaf(a, de, e2), fmaf(a, dd, d2));
                ((float2*)outv)[((size_t)b * NSYM + t) * MM + m] = v;
            }
        } else {
            const float2* scr = (const float2*)g_scratch + (size_t)b * 2 * MM;
            float2 e2  = make_float2(rb[m], ib[m]);
            float2 e11 = make_float2(rb[MM + m], ib[MM + m]);
            float2 d2  = scr[m], d11 = scr[MM + m];
            float2 de = csub(e11, e2), dd = csub(d11, d2);
            #pragma unroll
            for (int t = 3; t <= 10; ++t) {
                float a = (float)(t - 2) * (1.0f / 9.0f);
                float4 v = make_float4(fmaf(a, de.x, e2.x), fmaf(a, de.y, e2.y),
                                       fmaf(a, dd.x, d2.x), fmaf(a, dd.y, d2.y));
                ((float4*)outv)[((size_t)b * NSYM + t) * MM + m] = v;
            }
        }
    }
}

extern "C" void kernel_launch(void* const* d_in, const int* in_sizes, int n_in,
                              void* d_out, int out_size)
{
    const float* re = (const float*)d_in[0];
    const float* im = (const float*)d_in[1];
    const int B = in_sizes[0] / 4096;
    const long long interleaved = (long long)B * NSYM * 4096 * 2;

    if ((long long)out_size >= interleaved) {
        tdi_fft_kernel<1><<<2 * B, 256>>>(re, im, d_out);
        tdi_lerp_kernel<1><<<4 * B, 256>>>(re, im, d_out);
    } else {
        tdi_fft_kernel<0><<<2 * B, 256>>>(re, im, d_out);
        tdi_lerp_kernel<0><<<4 * B, 256>>>(re, im, d_out);
    }
}

// round 14
// speedup vs baseline: 1.1896x; 1.1341x over previous
#include <cuda_runtime.h>

// TransformDomainInterpolator, GB300 (sm_103a). Shuffle-FFT + streaming lerp.
//
// Math: fc = M/2 keeps ALL 2048 DFT bins -> exact 2x bandlimited interp:
//   out[2m]   = x[m]
//   out[2m+1] = IDFT2048( DFT2048(x)[k] * w[k] )/2048,
//     w[k] = e^{+i*pi*k/2048} (k<1024), -e^{+i*pi*k/2048} (k>=1024)
// Time: out[t] = lerp(H2, H11, clamp((t-2)/9, 0, 1)).
//
// k1 (per-(batch,row) FFT, 1024 blocks x 256 thr): position bits
// m=[b10..b0], thread=b7..b0 (lane=b4..b0, warp=b7b6b5), regs=b10b9b8.
// fwd 10,9,8 in regs | smem transpose (b10b9b8<->b7b6b5) | fwd 7,6,5 in
// regs | fwd 4..1 shfl_xor | mid (s0+pointwise+s0) shfl | inv 1..4 shfl |
// inv 5,6,7 regs | transpose back | inv 8,9,10 regs -> natural in regs.
// Only 2 smem data passes, 4 barriers. k2: lerp t=3..10, float4 stores.

#define MM 2048
#define NSYM 14
#define PADN 2176
#define PIDX(i) ((i) + ((i) >> 4))

__device__ float g_scratch[512 * 4096 * 2];

static __device__ __forceinline__ float2 cmul(float2 a, float2 b) {
    return make_float2(fmaf(a.x, b.x, -a.y * b.y), fmaf(a.x, b.y, a.y * b.x));
}
static __device__ __forceinline__ float2 cadd(float2 a, float2 b) {
    return make_float2(a.x + b.x, a.y + b.y);
}
static __device__ __forceinline__ float2 csub(float2 a, float2 b) {
    return make_float2(a.x - b.x, a.y - b.y);
}
static __device__ __forceinline__ float2 shflx(float2 v, int mask) {
    return make_float2(__shfl_xor_sync(0xffffffffu, v.x, mask),
                       __shfl_xor_sync(0xffffffffu, v.y, mask));
}

// 3 forward DIF register stages on reg bits (hi,mid,lo) of x[8].
// wa_r: hi-stage twiddle for top r (r=0..3); wb0: mid-stage (top bit 0);
// mid-stage top bit 1 uses -i*wb0; wc: lo-stage (all pairs).
static __device__ __forceinline__ void fwd3(float2* __restrict__ x,
    float2 wa0, float2 wa1, float2 wa2, float2 wa3, float2 wb0, float2 wc)
{
    { float2 u=x[0], v=x[4]; x[0]=cadd(u,v); x[4]=cmul(csub(u,v), wa0); }
    { float2 u=x[1], v=x[5]; x[1]=cadd(u,v); x[5]=cmul(csub(u,v), wa1); }
    { float2 u=x[2], v=x[6]; x[2]=cadd(u,v); x[6]=cmul(csub(u,v), wa2); }
    { float2 u=x[3], v=x[7]; x[3]=cadd(u,v); x[7]=cmul(csub(u,v), wa3); }
    float2 wb1 = make_float2(wb0.y, -wb0.x);          // -i * wb0
    #pragma unroll
    for (int o = 0; o < 8; o += 4) {
        float2 u=x[o],   v=x[o+2]; x[o]=cadd(u,v);   x[o+2]=cmul(csub(u,v), wb0);
        u=x[o+1]; v=x[o+3];        x[o+1]=cadd(u,v); x[o+3]=cmul(csub(u,v), wb1);
    }
    #pragma unroll
    for (int g = 0; g < 4; ++g) {
        float2 u=x[2*g], v=x[2*g+1];
        x[2*g]=cadd(u,v); x[2*g+1]=cmul(csub(u,v), wc);
    }
}

// 3 inverse DIT register stages (lo,mid,hi), conjugate twiddles.
static __device__ __forceinline__ void inv3(float2* __restrict__ x,
    float2 wa0, float2 wa1, float2 wa2, float2 wa3, float2 wb0, float2 wc)
{
    float2 cwc = make_float2(wc.x, -wc.y);
    #pragma unroll
    for (int g = 0; g < 4; ++g) {
        float2 t = cmul(x[2*g+1], cwc);
        float2 u = x[2*g];
        x[2*g]=cadd(u,t); x[2*g+1]=csub(u,t);
    }
    float2 cwb0 = make_float2(wb0.x, -wb0.y);
    float2 cwb1 = make_float2(wb0.y,  wb0.x);         // conj(-i*wb0)
    #pragma unroll
    for (int o = 0; o < 8; o += 4) {
        float2 t = cmul(x[o+2], cwb0); float2 u = x[o];
        x[o]=cadd(u,t); x[o+2]=csub(u,t);
        t = cmul(x[o+3], cwb1); u = x[o+1];
        x[o+1]=cadd(u,t); x[o+3]=csub(u,t);
    }
    { float2 t=cmul(x[4], make_float2(wa0.x,-wa0.y)); float2 u=x[0]; x[0]=cadd(u,t); x[4]=csub(u,t); }
    { float2 t=cmul(x[5], make_float2(wa1.x,-wa1.y)); float2 u=x[1]; x[1]=cadd(u,t); x[5]=csub(u,t); }
    { float2 t=cmul(x[6], make_float2(wa2.x,-wa2.y)); float2 u=x[2]; x[2]=cadd(u,t); x[6]=csub(u,t); }
    { float2 t=cmul(x[7], make_float2(wa3.x,-wa3.y)); float2 u=x[3]; x[3]=cadd(u,t); x[7]=csub(u,t); }
}

// ============================ k1: per-row FFT ============================
template <int MODE>
__global__ void __launch_bounds__(256) tdi_fft_kernel(
    const float* __restrict__ re,
    const float* __restrict__ im,
    void* __restrict__ outv)
{
    __shared__ float2 tw[1024];      // tw[t] = e^{-i*pi*t/1024}
    __shared__ float2 ys[PADN];

    const int batch = blockIdx.x >> 1;
    const int row   = blockIdx.x & 1;
    const int q8    = threadIdx.x;          // b7..b0
    const int lane  = q8 & 31;              // b4..b0
    const int w3    = q8 >> 5;              // phase-B: b10b9b8

    for (int t = q8; t < 1024; t += 256) {
        float s, c;
        sincospif(-(float)t * (1.0f / 1024.0f), &s, &c);
        tw[t] = make_float2(c, s);
    }

    const float* rbr = re + (size_t)batch * 4096 + row * MM;
    const float* ibr = im + (size_t)batch * 4096 + row * MM;

    float2 x[8];
    #pragma unroll
    for (int r = 0; r < 8; ++r) {
        int m = q8 + 256 * r;
        x[r] = make_float2(rbr[m], ibr[m]);
    }
    __syncthreads();                         // tw ready

    // ---- fwd stages 10,9,8 on regs (b10b9b8); j built from q8
    fwd3(x, tw[q8], tw[q8+256], tw[q8+512], tw[q8+768], tw[2*q8], tw[4*q8]);

    // ---- transpose: (b10b9b8) -> regs become (b7b6b5)
    #pragma unroll
    for (int r = 0; r < 8; ++r) ys[PIDX(q8 + 256 * r)] = x[r];
    __syncthreads();
    #pragma unroll
    for (int r = 0; r < 8; ++r) x[r] = ys[PIDX(w3 * 256 + r * 32 + lane)];

    // ---- fwd stages 7,6,5 on regs (b7b6b5); j built from lane
    fwd3(x, tw[8*lane], tw[8*lane+256], tw[8*lane+512], tw[8*lane+768],
         tw[16*lane], tw[32*lane]);

    // ---- fwd stages 4..1: shfl_xor on lane bits
    #pragma unroll
    for (int s = 4; s >= 1; --s) {
        int mask = 1 << s;
        float2 w = tw[(lane & (mask - 1)) << (10 - s)];
        bool bot = (lane & mask) != 0;
        #pragma unroll
        for (int r = 0; r < 8; ++r) {
            float2 o = shflx(x[r], mask);
            if (bot) x[r] = cmul(csub(o, x[r]), w);
            else     x[r] = cadd(x[r], o);
        }
    }

    // ---- MID: fwd s0 (w=1) + pointwise + inv s0 (w=1), via shfl mask 1
    {
        bool odd = (lane & 1) != 0;
        #pragma unroll
        for (int r = 0; r < 8; ++r) {
            float2 o = shflx(x[r], 1);
            x[r] = odd ? csub(o, x[r]) : cadd(x[r], o);
        }
        // k = 64*brev5(lane) + 8*brev3(r') + brev3(w3); sgn=(-1)^{b0}
        int kbase = 64 * (int)(__brev((unsigned)lane) >> 27)
                  + (int)(__brev((unsigned)w3) >> 29);
        float sv, cv;
        sincospif((float)kbase * (1.0f / 2048.0f), &sv, &cv);
        float ss = odd ? -(1.0f / 2048.0f) : (1.0f / 2048.0f);
        float2 baseW = make_float2(cv * ss, sv * ss);
        // C[r'] = e^{i*pi*brev3(r')/256}
        const float2 CPW[8] = {
            {1.000000000f, 0.000000000f},
            {0.998795456f, 0.049067674f},
            {0.999698819f, 0.024541229f},
            {0.997290457f, 0.073564564f},
            {0.999924702f, 0.012271538f},
            {0.998118113f, 0.061320736f},
            {0.999322385f, 0.036807223f},
            {0.996312612f, 0.085797312f}};
        #pragma unroll
        for (int r = 0; r < 8; ++r) x[r] = cmul(x[r], cmul(baseW, CPW[r]));
        #pragma unroll
        for (int r = 0; r < 8; ++r) {
            float2 o = shflx(x[r], 1);
            x[r] = odd ? csub(o, x[r]) : cadd(x[r], o);
        }
    }

    // ---- inv stages 1..4: shfl_xor, conjugate twiddles
    #pragma unroll
    for (int s = 1; s <= 4; ++s) {
        int mask = 1 << s;
        float2 w0 = tw[(lane & (mask - 1)) << (10 - s)];
        float2 cw = make_float2(w0.x, -w0.y);
        bool bot = (lane & mask) != 0;
        #pragma unroll
        for (int r = 0; r < 8; ++r) {
            float2 o = shflx(x[r], mask);
            if (bot) x[r] = csub(o, cmul(x[r], cw));
            else     x[r] = cadd(x[r], cmul(o, cw));
        }
    }

    // ---- inv stages 5,6,7 on regs (b7b6b5)
    inv3(x, tw[8*lane], tw[8*lane+256], tw[8*lane+512], tw[8*lane+768],
         tw[16*lane], tw[32*lane]);

    // ---- transpose back: regs -> (b10b9b8)
    __syncthreads();                         // all phase-B reads of ys done
    #pragma unroll
    for (int r = 0; r < 8; ++r) ys[PIDX(w3 * 256 + r * 32 + lane)] = x[r];
    __syncthreads();
    #pragma unroll
    for (int r = 0; r < 8; ++r) x[r] = ys[PIDX(q8 + 256 * r)];

    // ---- inv stages 8,9,10 on regs -> natural m = q8 + 256*r
    inv3(x, tw[q8], tw[q8+256], tw[q8+512], tw[q8+768], tw[2*q8], tw[4*q8]);

    // ---- epilogue: scratch + 3 row-exclusive symbols, all from registers
    const int t0 = row ? 11 : 0;
    if (MODE == 0) {
        float* scr = g_scratch + ((size_t)batch * 2 + row) * MM;
        #pragma unroll
        for (int r = 0; r < 8; ++r) {
            int m = q8 + 256 * r;
            float d = x[r].x;
            scr[m] = d;
            float2 v = make_float2(rbr[m], d);
            #pragma unroll
            for (int tt = 0; tt < 3; ++tt)
                ((float2*)outv)[((size_t)batch * NSYM + t0 + tt) * MM + m] = v;
        }
    } else {
        float2* scr = (float2*)g_scratch + ((size_t)batch * 2 + row) * MM;
        #pragma unroll
        for (int r = 0; r < 8; ++r) {
            int m = q8 + 256 * r;
            scr[m] = x[r];
            float4 v = make_float4(rbr[m], ibr[m], x[r].x, x[r].y);
            #pragma unroll
            for (int tt = 0; tt < 3; ++tt)
                ((float4*)outv)[((size_t)batch * NSYM + t0 + tt) * MM + m] = v;
        }
    }
}

// ===================== k2: streaming lerp, t = 3..10 =====================
template <int MODE>
__global__ void __launch_bounds__(256) tdi_lerp_kernel(
    const float* __restrict__ re,
    const float* __restrict__ im,
    void* __restrict__ outv)
{
    const int b    = blockIdx.x >> 2;
    const int part = blockIdx.x & 3;
    const int tid  = threadIdx.x;

    if (MODE == 0) {
        // pair index i covers subcarrier quad 4i..4i+3 (one float4 store)
        int i = part * 256 + tid;            // 0..1023
        const float2* rb2  = (const float2*)(re + (size_t)b * 4096);
        const float2* scr2 = (const float2*)(g_scratch + (size_t)b * 2 * MM);
        float2 e2  = rb2[i],        e11 = rb2[1024 + i];
        float2 d2  = scr2[i],       d11 = scr2[1024 + i];
        float2 de = csub(e11, e2), dd = csub(d11, d2);
        #pragma unroll
        for (int t = 3; t <= 10; ++t) {
            float a = (float)(t - 2) * (1.0f / 9.0f);
            float4 v = make_float4(fmaf(a, de.x, e2.x), fmaf(a, dd.x, d2.x),
                                   fmaf(a, de.y, e2.y), fmaf(a, dd.y, d2.y));
            ((float4*)outv)[((size_t)b * NSYM + t) * 1024 + i] = v;
        }
    } else {
        const float* rb = re + (size_t)b * 4096;
        const float* ib = im + (size_t)b * 4096;
        #pragma unroll
        for (int s = 0; s < 2; ++s) {
            int m = part * 512 + tid + 256 * s;
            const float2* scr = (const float2*)g_scratch + (size_t)b * 2 * MM;
            float2 e2  = make_float2(rb[m], ib[m]);
            float2 e11 = make_float2(rb[MM + m], ib[MM + m]);
            float2 d2 = scr[m], d11 = scr[MM + m];
            float2 de = csub(e11, e2), dd = csub(d11, d2);
            #pragma unroll
            for (int t = 3; t <= 10; ++t) {
                float a = (float)(t - 2) * (1.0f / 9.0f);
                float4 v = make_float4(fmaf(a, de.x, e2.x), fmaf(a, de.y, e2.y),
                                       fmaf(a, dd.x, d2.x), fmaf(a, dd.y, d2.y));
                ((float4*)outv)[((size_t)b * NSYM + t) * MM + m] = v;
            }
        }
    }
}

extern "C" void kernel_launch(void* const* d_in, const int* in_sizes, int n_in,
                              void* d_out, int out_size)
{
    const float* re = (const float*)d_in[0];
    const float* im = (const float*)d_in[1];
    const int B = in_sizes[0] / 4096;
    const long long interleaved = (long long)B * NSYM * 4096 * 2;

    if ((long long)out_size >= interleaved) {
        tdi_fft_kernel<1><<<2 * B, 256>>>(re, im, d_out);
        tdi_lerp_kernel<1><<<4 * B, 256>>>(re, im, d_out);
    } else {
        tdi_fft_kernel<0><<<2 * B, 256>>>(re, im, d_out);
        tdi_lerp_kernel<0><<<4 * B, 256>>>(re, im, d_out);
    }
}